// round 15
// baseline (speedup 1.0000x reference)
#include <cuda_runtime.h>
#include <cuda_fp16.h>
#include <math.h>
#include <stdint.h>

// ---------------------------------------------------------------------------
// Problem constants
// ---------------------------------------------------------------------------
#define B_  4
#define S_  2048
#define D_  1024
#define H_  16
#define DH_ 64
#define FF_ 4096
#define M_  (B_ * S_)          // 8192 rows
#define KVCH 16

// ---------------------------------------------------------------------------
// Scratch (device globals)
// ---------------------------------------------------------------------------
__device__ __half g_h2[M_ * 2 * D_];            // LN output, split (hi | lo)
__device__ __half g_attn2[M_ * 2 * D_];         // attention output, split
__device__ __half g_a1[(size_t)M_ * FF_];       // lookup out, fp16 single
__device__ float g_qkv[(size_t)M_ * 3 * D_];    // fused q|k|v (phi on q,k)
__device__ float g_x2[M_ * D_];
__device__ float g_kv[B_ * H_ * DH_ * DH_];
__device__ float g_z[B_ * H_ * DH_];
__device__ float g_kvpart[KVCH * B_ * H_ * DH_ * DH_];
__device__ float g_zpart[KVCH * B_ * H_ * DH_];
// transposed fp16 weights (K-major rows: wt[n,k] = w[k,n])
__device__ __half g_wqkvt[3 * D_ * D_];
__device__ __half g_wot[D_ * D_];
__device__ __half g_w1t[FF_ * D_];
__device__ __half g_w2t[D_ * FF_];

// ---------------------------------------------------------------------------
// PTX helpers (portable ISA: cp.async, ldmatrix, mma.sync)
// ---------------------------------------------------------------------------
__device__ __forceinline__ uint32_t smem_u32(const void* p) {
    uint32_t a;
    asm("{ .reg .u64 t; cvta.to.shared.u64 t, %1; cvt.u32.u64 %0, t; }"
        : "=r"(a) : "l"(p));
    return a;
}
__device__ __forceinline__ void cp_async16(uint32_t dst, const void* src) {
    asm volatile("cp.async.cg.shared.global [%0], [%1], 16;" :: "r"(dst), "l"(src));
}
#define CP_COMMIT() asm volatile("cp.async.commit_group;" ::: "memory")
template <int N>
__device__ __forceinline__ void cp_wait() {
    asm volatile("cp.async.wait_group %0;" :: "n"(N) : "memory");
}
__device__ __forceinline__ void ldm_x4(uint32_t& r0, uint32_t& r1, uint32_t& r2,
                                       uint32_t& r3, uint32_t addr) {
    asm volatile("ldmatrix.sync.aligned.m8n8.x4.shared.b16 {%0,%1,%2,%3}, [%4];"
                 : "=r"(r0), "=r"(r1), "=r"(r2), "=r"(r3) : "r"(addr));
}
__device__ __forceinline__ void mma_f16(float& c0, float& c1, float& c2, float& c3,
                                        uint32_t a0, uint32_t a1, uint32_t a2,
                                        uint32_t a3, uint32_t b0, uint32_t b1) {
    asm volatile(
        "mma.sync.aligned.m16n8k16.row.col.f32.f16.f16.f32 "
        "{%0,%1,%2,%3}, {%4,%5,%6,%7}, {%8,%9}, {%0,%1,%2,%3};"
        : "+f"(c0), "+f"(c1), "+f"(c2), "+f"(c3)
        : "r"(a0), "r"(a1), "r"(a2), "r"(a3), "r"(b0), "r"(b1));
}
__device__ __forceinline__ uint32_t swz(uint32_t o) { return o ^ ((o >> 3) & 0x70u); }

// ---------------------------------------------------------------------------
// Math helpers
// ---------------------------------------------------------------------------
__device__ __forceinline__ float phi_fn(float v) {
    return v > 0.0f ? v + 1.0f : expf(v);
}
__device__ __forceinline__ float lookup_gelu(float v) {
    float r = rintf(__fdiv_rn(v, 0.1f));
    r = fminf(fmaxf(r, -128.0f), 127.0f);
    float xq = r * 0.1f;
    float inner = 0.7978845608028654f * (xq + 0.044715f * xq * xq * xq);
    return 0.5f * xq * (1.0f + tanhf(inner));
}
__device__ __forceinline__ void split_f16(float v, __half& hi, __half& lo) {
    hi = __float2half_rn(v);
    lo = __float2half_rn(v - __half2float(hi));
}

// ---------------------------------------------------------------------------
// fp16 split GEMM via mma.sync (tile GBMT x GBNT, both templated):
//   NA=2: C = Ahi @ W^T + Alo @ W^T, A2 fp16 [M, 2K] (hi | lo)
//   NA=1: C = A @ W^T,               A2 fp16 [M, K]
//   Bt fp16 [Ntot, K] (K-major)
// BK=64, 3-stage cp.async, 256 threads, warps 2 x 4:
//   warp tile (GBMT/2) x (GBNT/4)
// EPI: 1 phi cols<phiN ->f32 | 2 +res ->f32 | 3 lookup -> fp16 single
// ---------------------------------------------------------------------------
#define KC  64
#define NSTG 3
#define TILE_A_(GBMT)   ((GBMT) * 128)
#define TILE_B_(GBNT)   ((GBNT) * 128)
#define STG_BYTES_(NA, GBMT, GBNT)  (TILE_B_(GBNT) + (NA) * TILE_A_(GBMT))
#define SMEM_TOTAL_(NA, GBMT, GBNT) (NSTG * STG_BYTES_(NA, GBMT, GBNT))

template <int EPI, int NA, int GBMT, int GBNT>
__global__ __launch_bounds__(256, 1)
void mma_gemm(const __half* __restrict__ A2, const __half* __restrict__ Bt,
              int K, int Ntot, int phiN, const float* __restrict__ res,
              float* __restrict__ outF, __half* __restrict__ outS)
{
    constexpr int STG_BYTES = STG_BYTES_(NA, GBMT, GBNT);
    constexpr int WM  = GBMT / 2;                // warp row height
    constexpr int WN  = GBNT / 4;                // warp col width
    constexpr int MAT = GBMT / 32;               // m16-atoms per warp
    constexpr int NAT = GBNT / 32;               // n8-atoms per warp
    constexpr int OFF_AH = TILE_B_(GBNT);
    constexpr int OFF_AL = TILE_B_(GBNT) + TILE_A_(GBMT);
    extern __shared__ char smem[];
    const uint32_t sb = smem_u32(smem);
    const int tid = threadIdx.x;
    const int wid = tid >> 5;
    const int lane = tid & 31;
    const int wr = wid >> 2;          // 0..1
    const int wc = wid & 3;           // 0..3
    const int row0 = blockIdx.y * GBMT;
    const int col0 = blockIdx.x * GBNT;
    const int lda = NA * K;
    const int C = K / KC;

    const int g = lane >> 3;
    const int l8 = lane & 7;
    const int a_row = wr * WM + (g & 1) * 8 + l8;
    const int a_kb  = (g >> 1) * 16;
    const int b_row = wc * WN + (g >> 1) * 8 + l8;
    const int b_kb  = (g & 1) * 16;

    float acc[MAT][NAT][4];
    #pragma unroll
    for (int i = 0; i < MAT; i++)
        #pragma unroll
        for (int j = 0; j < NAT; j++)
            #pragma unroll
            for (int t = 0; t < 4; t++) acc[i][j][t] = 0.0f;

    auto load_chunk = [&](int c, int s) {
        const uint32_t st = sb + s * STG_BYTES;
        const int k0 = c * KC;
        #pragma unroll
        for (int i = 0; i < NAT; ++i) {           // B: GBNT*8 segs / 256 thr
            int seg = i * 256 + tid;
            int r = seg >> 3, c8 = seg & 7;
            cp_async16(st + swz(r * 128 + c8 * 16),
                       Bt + (size_t)(col0 + r) * K + k0 + c8 * 8);
        }
        #pragma unroll
        for (int i = 0; i < MAT; ++i) {           // A: GBMT*8 segs / 256 thr
            int seg = i * 256 + tid;
            int r = seg >> 3, c8 = seg & 7;
            uint32_t doff = swz(r * 128 + c8 * 16);
            const __half* ah = A2 + (size_t)(row0 + r) * lda + k0 + c8 * 8;
            cp_async16(st + OFF_AH + doff, ah);
            if (NA == 2) cp_async16(st + OFF_AL + doff, ah + K);
        }
        CP_COMMIT();
    };

    load_chunk(0, 0);
    if (C > 1) load_chunk(1, 1);
    if (C > 2) load_chunk(2, 2);

    for (int c = 0; c < C; ++c) {
        const int s = c % NSTG;
        if (c + 3 <= C) cp_wait<2>();
        else if (c + 2 == C) cp_wait<1>();
        else cp_wait<0>();
        __syncthreads();

        const uint32_t st = sb + s * STG_BYTES;
        const uint32_t ahb = st + OFF_AH;
        const uint32_t alb = st + OFF_AL;
        const uint32_t bbb = st;

        #pragma unroll
        for (int ks = 0; ks < 4; ++ks) {
            const int kb = ks * 32;
            uint32_t bf[NAT][2];
            #pragma unroll
            for (int nb = 0; nb < NAT / 2; ++nb) {
                uint32_t addr = bbb + swz((b_row + nb * 16) * 128 + kb + b_kb);
                ldm_x4(bf[nb * 2][0], bf[nb * 2][1],
                       bf[nb * 2 + 1][0], bf[nb * 2 + 1][1], addr);
            }
            // hi plane
            #pragma unroll
            for (int ma = 0; ma < MAT; ++ma) {
                uint32_t a0, a1, a2, a3;
                ldm_x4(a0, a1, a2, a3,
                       ahb + swz((a_row + ma * 16) * 128 + kb + a_kb));
                #pragma unroll
                for (int na = 0; na < NAT; ++na)
                    mma_f16(acc[ma][na][0], acc[ma][na][1],
                            acc[ma][na][2], acc[ma][na][3],
                            a0, a1, a2, a3, bf[na][0], bf[na][1]);
            }
            // lo plane
            if (NA == 2) {
                #pragma unroll
                for (int ma = 0; ma < MAT; ++ma) {
                    uint32_t a0, a1, a2, a3;
                    ldm_x4(a0, a1, a2, a3,
                           alb + swz((a_row + ma * 16) * 128 + kb + a_kb));
                    #pragma unroll
                    for (int na = 0; na < NAT; ++na)
                        mma_f16(acc[ma][na][0], acc[ma][na][1],
                                acc[ma][na][2], acc[ma][na][3],
                                a0, a1, a2, a3, bf[na][0], bf[na][1]);
                }
            }
        }
        __syncthreads();
        if (c + 3 < C) load_chunk(c + 3, s);
    }

    // Epilogue
    const int er = row0 + wr * WM + (lane >> 2);
    const int ec = col0 + wc * WN + (lane & 3) * 2;
    #pragma unroll
    for (int ma = 0; ma < MAT; ++ma) {
        #pragma unroll
        for (int na = 0; na < NAT; ++na) {
            const int r0r = er + ma * 16;
            const int cc = ec + na * 8;
            #pragma unroll
            for (int half_ = 0; half_ < 2; ++half_) {
                const int rr = r0r + half_ * 8;
                float v0 = acc[ma][na][half_ * 2 + 0];
                float v1 = acc[ma][na][half_ * 2 + 1];
                if (EPI == 3) {
                    v0 = lookup_gelu(v0);
                    v1 = lookup_gelu(v1);
                    *reinterpret_cast<__half2*>(outS + (size_t)rr * Ntot + cc) =
                        __floats2half2_rn(v0, v1);
                } else {
                    if (EPI == 1 && cc < phiN) { v0 = phi_fn(v0); v1 = phi_fn(v1); }
                    if (EPI == 2) {
                        const float2 rv = *reinterpret_cast<const float2*>(
                            res + (size_t)rr * Ntot + cc);
                        v0 += rv.x; v1 += rv.y;
                    }
                    float2 o; o.x = v0; o.y = v1;
                    *reinterpret_cast<float2*>(outF + (size_t)rr * Ntot + cc) = o;
                }
            }
        }
    }
}

// ---------------------------------------------------------------------------
// Batched weight transpose + fp16 convert (all 6 weights, one launch)
// ---------------------------------------------------------------------------
__global__ __launch_bounds__(256)
void transpose_all(const float* __restrict__ wq, const float* __restrict__ wk,
                   const float* __restrict__ wv, const float* __restrict__ wo,
                   const float* __restrict__ w1, const float* __restrict__ w2,
                   __half* __restrict__ wqkvt, __half* __restrict__ wot,
                   __half* __restrict__ w1t, __half* __restrict__ w2t)
{
    const int b = blockIdx.x;
    const float* src;
    __half* dst;
    int K, N, k0, n0;
    if (b < 4096) {
        const int w = b >> 10, r = b & 1023;
        K = 1024; N = 1024;
        src = (w == 0) ? wq : (w == 1) ? wk : (w == 2) ? wv : wo;
        dst = (w < 3) ? (wqkvt + (size_t)w * D_ * D_) : wot;
        k0 = (r & 31) * 32; n0 = (r >> 5) * 32;
    } else if (b < 8192) {
        const int r = b - 4096;
        K = 1024; N = 4096; src = w1; dst = w1t;
        k0 = (r & 31) * 32; n0 = (r >> 5) * 32;
    } else {
        const int r = b - 8192;
        K = 4096; N = 1024; src = w2; dst = w2t;
        k0 = (r & 127) * 32; n0 = (r >> 7) * 32;
    }

    __shared__ float t[32][33];
    const int tx = threadIdx.x & 31, ty = threadIdx.x >> 5;
    #pragma unroll
    for (int i = 0; i < 4; ++i)
        t[ty + i * 8][tx] = src[(size_t)(k0 + ty + i * 8) * N + n0 + tx];
    __syncthreads();
    #pragma unroll
    for (int i = 0; i < 4; ++i)
        dst[(size_t)(n0 + ty + i * 8) * K + k0 + tx] =
            __float2half_rn(t[tx][ty + i * 8]);
}

// ---------------------------------------------------------------------------
// LayerNorm -> split fp16 [M, 2*D]
// ---------------------------------------------------------------------------
__global__ __launch_bounds__(256)
void ln_split_kernel(const float* __restrict__ x, const float* __restrict__ g,
                     const float* __restrict__ bb, __half* __restrict__ y2)
{
    __shared__ float red[8];
    const int row = blockIdx.x;
    const int tid = threadIdx.x;
    float4 v = reinterpret_cast<const float4*>(x + (size_t)row * D_)[tid];

    float s = v.x + v.y + v.z + v.w;
    #pragma unroll
    for (int o = 16; o > 0; o >>= 1) s += __shfl_xor_sync(0xffffffffu, s, o);
    if ((tid & 31) == 0) red[tid >> 5] = s;
    __syncthreads();
    s = 0.0f;
    #pragma unroll
    for (int i = 0; i < 8; i++) s += red[i];
    const float mean = s * (1.0f / D_);
    __syncthreads();

    float d0 = v.x - mean, d1 = v.y - mean, d2 = v.z - mean, d3 = v.w - mean;
    float s2 = d0 * d0 + d1 * d1 + d2 * d2 + d3 * d3;
    #pragma unroll
    for (int o = 16; o > 0; o >>= 1) s2 += __shfl_xor_sync(0xffffffffu, s2, o);
    if ((tid & 31) == 0) red[tid >> 5] = s2;
    __syncthreads();
    s2 = 0.0f;
    #pragma unroll
    for (int i = 0; i < 8; i++) s2 += red[i];
    const float rs = rsqrtf(s2 * (1.0f / D_) + 1e-5f);

    float4 gg = reinterpret_cast<const float4*>(g)[tid];
    float4 bv = reinterpret_cast<const float4*>(bb)[tid];
    float o0 = d0 * rs * gg.x + bv.x;
    float o1 = d1 * rs * gg.y + bv.y;
    float o2 = d2 * rs * gg.z + bv.z;
    float o3 = d3 * rs * gg.w + bv.w;

    size_t base = (size_t)row * (2 * D_) + tid * 4;
    __half h0, l0, h1, l1, h2, l2, h3, l3;
    split_f16(o0, h0, l0); split_f16(o1, h1, l1);
    split_f16(o2, h2, l2); split_f16(o3, h3, l3);
    __half2 hp0; hp0.x = h0; hp0.y = h1;
    __half2 hp1; hp1.x = h2; hp1.y = h3;
    __half2 lp0; lp0.x = l0; lp0.y = l1;
    __half2 lp1; lp1.x = l2; lp1.y = l3;
    *reinterpret_cast<__half2*>(y2 + base) = hp0;
    *reinterpret_cast<__half2*>(y2 + base + 2) = hp1;
    *reinterpret_cast<__half2*>(y2 + base + D_) = lp0;
    *reinterpret_cast<__half2*>(y2 + base + D_ + 2) = lp1;
}

// ---------------------------------------------------------------------------
// kv partials: 128 threads = 2 groups x 64; each group: 8x8 per-thread tile
// over half the s-range (1.0 B LDS per FMA, half serial FMA per thread).
// Deterministic: final = group0_sum + group1_sum.
// grid (64 bh, KVCH chunks)
// ---------------------------------------------------------------------------
#define QKV_LD (3 * D_)
__global__ __launch_bounds__(128)
void kv_part_kernel(const float* __restrict__ qkv,
                    float* __restrict__ kvpart, float* __restrict__ zpart)
{
    const int bh = blockIdx.x;
    const int ch = blockIdx.y;
    const int b = bh >> 4, h = bh & 15;
    const int schunk = S_ / KVCH;        // 128
    const float* Kp = qkv + (size_t)b * S_ * QKV_LD + D_ + h * DH_
                      + (size_t)ch * schunk * QKV_LD;
    const float* Vp = Kp + D_;

    __shared__ float Ks[32][DH_];        // 8 KB
    __shared__ float Vs[32][DH_];        // 8 KB
    __shared__ float zc[DH_];

    const int tid = threadIdx.x;         // 0..127
    const int grp = tid >> 6;            // 0..1 : s-half
    const int gt  = tid & 63;
    const int tx = gt & 7, ty = gt >> 3; // 8x8 tile within 64x64

    float acc[8][8];
    #pragma unroll
    for (int i = 0; i < 8; i++)
        #pragma unroll
        for (int j = 0; j < 8; j++) acc[i][j] = 0.0f;
    float zacc = 0.0f;

    const int sBeg = grp * 16, sEnd = sBeg + 16;

    for (int s0 = 0; s0 < schunk; s0 += 32) {
        // load 32 rows x 64 floats of K and V: 512 float4 each / 128 thr = 4 each
        #pragma unroll
        for (int i = 0; i < 4; i++) {
            int jj = i * 128 + tid;       // 0..511
            int r = jj >> 4, c4 = jj & 15;
            *reinterpret_cast<float4*>(&Ks[r][c4 * 4]) =
                *reinterpret_cast<const float4*>(&Kp[(size_t)(s0 + r) * QKV_LD + c4 * 4]);
            *reinterpret_cast<float4*>(&Vs[r][c4 * 4]) =
                *reinterpret_cast<const float4*>(&Vp[(size_t)(s0 + r) * QKV_LD + c4 * 4]);
        }
        __syncthreads();
        #pragma unroll 4
        for (int s = sBeg; s < sEnd; s++) {
            float a[8], bv[8];
            *reinterpret_cast<float4*>(&a[0]) =
                *reinterpret_cast<const float4*>(&Ks[s][ty * 8]);
            *reinterpret_cast<float4*>(&a[4]) =
                *reinterpret_cast<const float4*>(&Ks[s][ty * 8 + 4]);
            *reinterpret_cast<float4*>(&bv[0]) =
                *reinterpret_cast<const float4*>(&Vs[s][tx * 8]);
            *reinterpret_cast<float4*>(&bv[4]) =
                *reinterpret_cast<const float4*>(&Vs[s][tx * 8 + 4]);
            #pragma unroll
            for (int i = 0; i < 8; i++)
                #pragma unroll
                for (int j = 0; j < 8; j++) acc[i][j] += a[i] * bv[j];
        }
        // z: each group sums its s-half for d = gt
        #pragma unroll 4
        for (int s = sBeg; s < sEnd; s++) zacc += Ks[s][gt];
        __syncthreads();
    }

    // Combine group1 into group0 via smem (reuse Ks/Vs as 64x64 buffer)
    float* comb = &Ks[0][0];             // 16 KB contiguous (Ks then Vs)
    if (grp == 1) {
        #pragma unroll
        for (int i = 0; i < 8; i++)
            #pragma unroll
            for (int j = 0; j < 8; j += 4)
                *reinterpret_cast<float4*>(&comb[(ty * 8 + i) * 64 + tx * 8 + j]) =
                    *reinterpret_cast<const float4*>(&acc[i][j]);
        zc[gt] = zacc;
    }
    __syncthreads();
    if (grp == 0) {
        float* kvp = kvpart + ((size_t)ch * 64 + bh) * DH_ * DH_;
        #pragma unroll
        for (int i = 0; i < 8; i++) {
            #pragma unroll
            for (int j = 0; j < 8; j += 4) {
                float4 o = *reinterpret_cast<const float4*>(
                    &comb[(ty * 8 + i) * 64 + tx * 8 + j]);
                o.x += acc[i][j + 0];
                o.y += acc[i][j + 1];
                o.z += acc[i][j + 2];
                o.w += acc[i][j + 3];
                // order: group0 + group1 (deterministic)
                float4 w;
                w.x = acc[i][j + 0] + (o.x - acc[i][j + 0]);
                w.y = acc[i][j + 1] + (o.y - acc[i][j + 1]);
                w.z = acc[i][j + 2] + (o.z - acc[i][j + 2]);
                w.w = acc[i][j + 3] + (o.w - acc[i][j + 3]);
                *reinterpret_cast<float4*>(
                    &kvp[(ty * 8 + i) * DH_ + tx * 8 + j]) = o;
                (void)w;
            }
        }
        zpart[((size_t)ch * 64 + bh) * DH_ + gt] = zacc + zc[gt];
    }
}

// Deterministic fixed-order reduce, parallelized: grid (64 bh, 4 slices)
__global__ __launch_bounds__(256)
void kv_reduce_kernel(const float* __restrict__ kvpart, const float* __restrict__ zpart,
                      float* __restrict__ kv, float* __restrict__ z)
{
    const int bh = blockIdx.x;
    const int sl = blockIdx.y;           // 0..3, each 1024 kv elements
    const int tid = threadIdx.x;
    const int idx0 = sl * 1024;
    #pragma unroll
    for (int i = 0; i < 4; ++i) {
        int idx = idx0 + i * 256 + tid;
        float s = 0.0f;
        #pragma unroll
        for (int ch = 0; ch < KVCH; ++ch)
            s += kvpart[((size_t)ch * 64 + bh) * DH_ * DH_ + idx];
        kv[(size_t)bh * DH_ * DH_ + idx] = s;
    }
    if (sl == 0 && tid < DH_) {
        float s = 0.0f;
        #pragma unroll
        for (int ch = 0; ch < KVCH; ++ch)
            s += zpart[((size_t)ch * 64 + bh) * DH_ + tid];
        z[bh * DH_ + tid] = s;
    }
}

// ---------------------------------------------------------------------------
// attn out -> split fp16 [M, 2*D]
// ---------------------------------------------------------------------------
__global__ __launch_bounds__(128)
void attn_kernel(const float* __restrict__ qkv, const float* __restrict__ kv,
                 const float* __restrict__ z, __half* __restrict__ out2)
{
    const int bh = blockIdx.x;
    const int b = bh >> 4, h = bh & 15;
    __shared__ float kvs[DH_ * DH_];
    __shared__ float zs[DH_];
    const int tid = threadIdx.x;

    const float4* kvg = reinterpret_cast<const float4*>(kv + (size_t)bh * DH_ * DH_);
    #pragma unroll
    for (int i = 0; i < 8; i++)
        reinterpret_cast<float4*>(kvs)[tid + i * 128] = kvg[tid + i * 128];
    if (tid < 16)
        reinterpret_cast<float4*>(zs)[tid] =
            reinterpret_cast<const float4*>(z + bh * DH_)[tid];
    __syncthreads();

    const int s = blockIdx.y * 128 + tid;
    const float* qr = qkv + (size_t)(b * S_ + s) * QKV_LD + h * DH_;
    float pq[DH_];
    #pragma unroll
    for (int i = 0; i < 16; i++)
        reinterpret_cast<float4*>(pq)[i] = reinterpret_cast<const float4*>(qr)[i];

    float acc[DH_];
    #pragma unroll
    for (int e = 0; e < DH_; e++) acc[e] = 0.0f;
    float den = 1e-6f;

    #pragma unroll 8
    for (int d = 0; d < DH_; d++) {
        float a = pq[d];
        den += a * zs[d];
        const float4* kr = reinterpret_cast<const float4*>(&kvs[d * DH_]);
        #pragma unroll
        for (int e4 = 0; e4 < 16; e4++) {
            float4 kk = kr[e4];
            acc[e4 * 4 + 0] += a * kk.x;
            acc[e4 * 4 + 1] += a * kk.y;
            acc[e4 * 4 + 2] += a * kk.z;
            acc[e4 * 4 + 3] += a * kk.w;
        }
    }

    const float inv = __fdiv_rn(1.0f, den);
    size_t base = (size_t)(b * S_ + s) * (2 * D_) + h * DH_;
    #pragma unroll
    for (int e = 0; e < DH_; e += 2) {
        __half h0, l0, h1, l1;
        split_f16(acc[e] * inv, h0, l0);
        split_f16(acc[e + 1] * inv, h1, l1);
        __half2 hp; hp.x = h0; hp.y = h1;
        __half2 lp; lp.x = l0; lp.y = l1;
        *reinterpret_cast<__half2*>(out2 + base + e) = hp;
        *reinterpret_cast<__half2*>(out2 + base + D_ + e) = lp;
    }
}

// ---------------------------------------------------------------------------
// Launch
// ---------------------------------------------------------------------------
extern "C" void kernel_launch(void* const* d_in, const int* in_sizes, int n_in,
                              void* d_out, int out_size)
{
    const float* x    = (const float*)d_in[0];
    const float* ln1g = (const float*)d_in[1];
    const float* ln1b = (const float*)d_in[2];
    const float* wq   = (const float*)d_in[3];
    const float* wk   = (const float*)d_in[4];
    const float* wv   = (const float*)d_in[5];
    const float* wo   = (const float*)d_in[6];
    const float* ln2g = (const float*)d_in[7];
    const float* ln2b = (const float*)d_in[8];
    const float* w1   = (const float*)d_in[9];
    const float* w2   = (const float*)d_in[10];
    float* out = (float*)d_out;

    __half *h2, *attn2, *a1, *wqkvt, *wot, *w1t, *w2t;
    float *qkv, *x2, *kvp, *zp, *kvpart, *zpart;
    cudaGetSymbolAddress((void**)&h2,     g_h2);
    cudaGetSymbolAddress((void**)&attn2,  g_attn2);
    cudaGetSymbolAddress((void**)&a1,     g_a1);
    cudaGetSymbolAddress((void**)&wqkvt,  g_wqkvt);
    cudaGetSymbolAddress((void**)&wot,    g_wot);
    cudaGetSymbolAddress((void**)&w1t,    g_w1t);
    cudaGetSymbolAddress((void**)&w2t,    g_w2t);
    cudaGetSymbolAddress((void**)&qkv,    g_qkv);
    cudaGetSymbolAddress((void**)&x2,     g_x2);
    cudaGetSymbolAddress((void**)&kvp,    g_kv);
    cudaGetSymbolAddress((void**)&zp,     g_z);
    cudaGetSymbolAddress((void**)&kvpart, g_kvpart);
    cudaGetSymbolAddress((void**)&zpart,  g_zpart);

    cudaFuncSetAttribute(mma_gemm<1, 2, 128, 192>,
                         cudaFuncAttributeMaxDynamicSharedMemorySize,
                         SMEM_TOTAL_(2, 128, 192));
    cudaFuncSetAttribute(mma_gemm<2, 2, 64, 128>,
                         cudaFuncAttributeMaxDynamicSharedMemorySize,
                         SMEM_TOTAL_(2, 64, 128));
    cudaFuncSetAttribute(mma_gemm<3, 2, 128, 256>,
                         cudaFuncAttributeMaxDynamicSharedMemorySize,
                         SMEM_TOTAL_(2, 128, 256));
    cudaFuncSetAttribute(mma_gemm<2, 1, 64, 128>,
                         cudaFuncAttributeMaxDynamicSharedMemorySize,
                         SMEM_TOTAL_(1, 64, 128));

    // 0. weight prep: one batched transpose launch
    transpose_all<<<12288, 256>>>(wq, wk, wv, wo, w1, w2, wqkvt, wot, w1t, w2t);

    // 1. h2 = split(LN1(x))
    ln_split_kernel<<<M_, 256>>>(x, ln1g, ln1b, h2);

    // 2. fused qkv = h2 @ [wq|wk|wv]; phi for cols < 2D (q,k). 1024 CTAs.
    dim3 gQKV(3 * D_ / 192, M_ / 128);
    mma_gemm<1, 2, 128, 192><<<gQKV, 256, SMEM_TOTAL_(2, 128, 192)>>>(
        h2, wqkvt, D_, 3 * D_, 2 * D_, nullptr, qkv, nullptr);

    // 3. kv/z partials (1024 CTAs, 2-group 8x8 tiles) + parallel reduce
    kv_part_kernel<<<dim3(B_ * H_, KVCH), 128>>>(qkv, kvpart, zpart);
    kv_reduce_kernel<<<dim3(B_ * H_, 4), 256>>>(kvpart, zpart, kvp, zp);

    // 4. attn -> split fp16
    attn_kernel<<<dim3(B_ * H_, S_ / 128), 128>>>(qkv, kvp, zp, attn2);

    // 5. x2 = x + attn @ wo   (64x128 tiles -> 1024 CTAs)
    dim3 gWO(D_ / 128, M_ / 64);
    mma_gemm<2, 2, 64, 128><<<gWO, 256, SMEM_TOTAL_(2, 64, 128)>>>(
        attn2, wot, D_, D_, 0, x, x2, nullptr);

    // 6. h2 = split(LN2(x2))
    ln_split_kernel<<<M_, 256>>>(x2, ln2g, ln2b, h2);

    // 7. a1 = fp16(lookup(h2 @ w1))  (128x256 tiles -> 1024 CTAs)
    dim3 gF(FF_ / 256, M_ / 128);
    mma_gemm<3, 2, 128, 256><<<gF, 256, SMEM_TOTAL_(2, 128, 256)>>>(
        h2, w1t, D_, FF_, 0, nullptr, nullptr, a1);

    // 8. out = x2 + a1 @ w2  (single fp16 A, 64x128 tiles -> 1024 CTAs)
    mma_gemm<2, 1, 64, 128><<<gWO, 256, SMEM_TOTAL_(1, 64, 128)>>>(
        a1, w2t, FF_, D_, 0, x2, out, nullptr);
}

// round 16
// speedup vs baseline: 1.0060x; 1.0060x over previous
#include <cuda_runtime.h>
#include <cuda_fp16.h>
#include <math.h>
#include <stdint.h>

// ---------------------------------------------------------------------------
// Problem constants
// ---------------------------------------------------------------------------
#define B_  4
#define S_  2048
#define D_  1024
#define H_  16
#define DH_ 64
#define FF_ 4096
#define M_  (B_ * S_)          // 8192 rows
#define KVCH 16

// ---------------------------------------------------------------------------
// Scratch (device globals)
// ---------------------------------------------------------------------------
__device__ __half g_h2[M_ * 2 * D_];            // LN output, split (hi | lo)
__device__ __half g_attn2[M_ * 2 * D_];         // attention output, split
__device__ __half g_a1[(size_t)M_ * FF_];       // lookup out, fp16 single
__device__ float g_qkv[(size_t)M_ * 3 * D_];    // fused q|k|v (phi on q,k)
__device__ float g_x2[M_ * D_];
__device__ float g_kv[B_ * H_ * DH_ * DH_];
__device__ float g_z[B_ * H_ * DH_];
__device__ float g_kvpart[KVCH * B_ * H_ * DH_ * DH_];
__device__ float g_zpart[KVCH * B_ * H_ * DH_];
// transposed fp16 weights (K-major rows: wt[n,k] = w[k,n])
__device__ __half g_wqkvt[3 * D_ * D_];
__device__ __half g_wot[D_ * D_];
__device__ __half g_w1t[FF_ * D_];
__device__ __half g_w2t[D_ * FF_];

// ---------------------------------------------------------------------------
// PTX helpers (portable ISA: cp.async, ldmatrix, mma.sync)
// ---------------------------------------------------------------------------
__device__ __forceinline__ uint32_t smem_u32(const void* p) {
    uint32_t a;
    asm("{ .reg .u64 t; cvta.to.shared.u64 t, %1; cvt.u32.u64 %0, t; }"
        : "=r"(a) : "l"(p));
    return a;
}
__device__ __forceinline__ void cp_async16(uint32_t dst, const void* src) {
    asm volatile("cp.async.cg.shared.global [%0], [%1], 16;" :: "r"(dst), "l"(src));
}
#define CP_COMMIT() asm volatile("cp.async.commit_group;" ::: "memory")
template <int N>
__device__ __forceinline__ void cp_wait() {
    asm volatile("cp.async.wait_group %0;" :: "n"(N) : "memory");
}
__device__ __forceinline__ void ldm_x4(uint32_t& r0, uint32_t& r1, uint32_t& r2,
                                       uint32_t& r3, uint32_t addr) {
    asm volatile("ldmatrix.sync.aligned.m8n8.x4.shared.b16 {%0,%1,%2,%3}, [%4];"
                 : "=r"(r0), "=r"(r1), "=r"(r2), "=r"(r3) : "r"(addr));
}
__device__ __forceinline__ void mma_f16(float& c0, float& c1, float& c2, float& c3,
                                        uint32_t a0, uint32_t a1, uint32_t a2,
                                        uint32_t a3, uint32_t b0, uint32_t b1) {
    asm volatile(
        "mma.sync.aligned.m16n8k16.row.col.f32.f16.f16.f32 "
        "{%0,%1,%2,%3}, {%4,%5,%6,%7}, {%8,%9}, {%0,%1,%2,%3};"
        : "+f"(c0), "+f"(c1), "+f"(c2), "+f"(c3)
        : "r"(a0), "r"(a1), "r"(a2), "r"(a3), "r"(b0), "r"(b1));
}
__device__ __forceinline__ uint32_t swz(uint32_t o) { return o ^ ((o >> 3) & 0x70u); }

// ---------------------------------------------------------------------------
// Math helpers
// ---------------------------------------------------------------------------
__device__ __forceinline__ float phi_fn(float v) {
    return v > 0.0f ? v + 1.0f : expf(v);
}
__device__ __forceinline__ float lookup_gelu(float v) {
    float r = rintf(__fdiv_rn(v, 0.1f));
    r = fminf(fmaxf(r, -128.0f), 127.0f);
    float xq = r * 0.1f;
    float inner = 0.7978845608028654f * (xq + 0.044715f * xq * xq * xq);
    return 0.5f * xq * (1.0f + tanhf(inner));
}
__device__ __forceinline__ void split_f16(float v, __half& hi, __half& lo) {
    hi = __float2half_rn(v);
    lo = __float2half_rn(v - __half2float(hi));
}

// ---------------------------------------------------------------------------
// LN body (shared by fused prep kernel and standalone LN kernel)
// ---------------------------------------------------------------------------
__device__ __forceinline__ void ln_row_body(const float* __restrict__ x,
                                            const float* __restrict__ g,
                                            const float* __restrict__ bb,
                                            __half* __restrict__ y2,
                                            int row, int tid, float* red)
{
    float4 v = reinterpret_cast<const float4*>(x + (size_t)row * D_)[tid];

    float s = v.x + v.y + v.z + v.w;
    #pragma unroll
    for (int o = 16; o > 0; o >>= 1) s += __shfl_xor_sync(0xffffffffu, s, o);
    if ((tid & 31) == 0) red[tid >> 5] = s;
    __syncthreads();
    s = 0.0f;
    #pragma unroll
    for (int i = 0; i < 8; i++) s += red[i];
    const float mean = s * (1.0f / D_);
    __syncthreads();

    float d0 = v.x - mean, d1 = v.y - mean, d2 = v.z - mean, d3 = v.w - mean;
    float s2 = d0 * d0 + d1 * d1 + d2 * d2 + d3 * d3;
    #pragma unroll
    for (int o = 16; o > 0; o >>= 1) s2 += __shfl_xor_sync(0xffffffffu, s2, o);
    if ((tid & 31) == 0) red[tid >> 5] = s2;
    __syncthreads();
    s2 = 0.0f;
    #pragma unroll
    for (int i = 0; i < 8; i++) s2 += red[i];
    const float rs = rsqrtf(s2 * (1.0f / D_) + 1e-5f);

    float4 gg = reinterpret_cast<const float4*>(g)[tid];
    float4 bv = reinterpret_cast<const float4*>(bb)[tid];
    float o0 = d0 * rs * gg.x + bv.x;
    float o1 = d1 * rs * gg.y + bv.y;
    float o2 = d2 * rs * gg.z + bv.z;
    float o3 = d3 * rs * gg.w + bv.w;

    size_t base = (size_t)row * (2 * D_) + tid * 4;
    __half h0, l0, h1, l1, h2, l2, h3, l3;
    split_f16(o0, h0, l0); split_f16(o1, h1, l1);
    split_f16(o2, h2, l2); split_f16(o3, h3, l3);
    __half2 hp0; hp0.x = h0; hp0.y = h1;
    __half2 hp1; hp1.x = h2; hp1.y = h3;
    __half2 lp0; lp0.x = l0; lp0.y = l1;
    __half2 lp1; lp1.x = l2; lp1.y = l3;
    *reinterpret_cast<__half2*>(y2 + base) = hp0;
    *reinterpret_cast<__half2*>(y2 + base + 2) = hp1;
    *reinterpret_cast<__half2*>(y2 + base + D_) = lp0;
    *reinterpret_cast<__half2*>(y2 + base + D_ + 2) = lp1;
}

// ---------------------------------------------------------------------------
// fp16 split GEMM via mma.sync (tile GBMT x GBNT, both templated)
// ---------------------------------------------------------------------------
#define KC  64
#define NSTG 3
#define TILE_A_(GBMT)   ((GBMT) * 128)
#define TILE_B_(GBNT)   ((GBNT) * 128)
#define STG_BYTES_(NA, GBMT, GBNT)  (TILE_B_(GBNT) + (NA) * TILE_A_(GBMT))
#define SMEM_TOTAL_(NA, GBMT, GBNT) (NSTG * STG_BYTES_(NA, GBMT, GBNT))

template <int EPI, int NA, int GBMT, int GBNT>
__global__ __launch_bounds__(256, 1)
void mma_gemm(const __half* __restrict__ A2, const __half* __restrict__ Bt,
              int K, int Ntot, int phiN, const float* __restrict__ res,
              float* __restrict__ outF, __half* __restrict__ outS)
{
    constexpr int STG_BYTES = STG_BYTES_(NA, GBMT, GBNT);
    constexpr int WM  = GBMT / 2;
    constexpr int WN  = GBNT / 4;
    constexpr int MAT = GBMT / 32;
    constexpr int NAT = GBNT / 32;
    constexpr int OFF_AH = TILE_B_(GBNT);
    constexpr int OFF_AL = TILE_B_(GBNT) + TILE_A_(GBMT);
    extern __shared__ char smem[];
    const uint32_t sb = smem_u32(smem);
    const int tid = threadIdx.x;
    const int wid = tid >> 5;
    const int lane = tid & 31;
    const int wr = wid >> 2;
    const int wc = wid & 3;
    const int row0 = blockIdx.y * GBMT;
    const int col0 = blockIdx.x * GBNT;
    const int lda = NA * K;
    const int C = K / KC;

    const int g = lane >> 3;
    const int l8 = lane & 7;
    const int a_row = wr * WM + (g & 1) * 8 + l8;
    const int a_kb  = (g >> 1) * 16;
    const int b_row = wc * WN + (g >> 1) * 8 + l8;
    const int b_kb  = (g & 1) * 16;

    float acc[MAT][NAT][4];
    #pragma unroll
    for (int i = 0; i < MAT; i++)
        #pragma unroll
        for (int j = 0; j < NAT; j++)
            #pragma unroll
            for (int t = 0; t < 4; t++) acc[i][j][t] = 0.0f;

    auto load_chunk = [&](int c, int s) {
        const uint32_t st = sb + s * STG_BYTES;
        const int k0 = c * KC;
        #pragma unroll
        for (int i = 0; i < NAT; ++i) {
            int seg = i * 256 + tid;
            int r = seg >> 3, c8 = seg & 7;
            cp_async16(st + swz(r * 128 + c8 * 16),
                       Bt + (size_t)(col0 + r) * K + k0 + c8 * 8);
        }
        #pragma unroll
        for (int i = 0; i < MAT; ++i) {
            int seg = i * 256 + tid;
            int r = seg >> 3, c8 = seg & 7;
            uint32_t doff = swz(r * 128 + c8 * 16);
            const __half* ah = A2 + (size_t)(row0 + r) * lda + k0 + c8 * 8;
            cp_async16(st + OFF_AH + doff, ah);
            if (NA == 2) cp_async16(st + OFF_AL + doff, ah + K);
        }
        CP_COMMIT();
    };

    load_chunk(0, 0);
    if (C > 1) load_chunk(1, 1);
    if (C > 2) load_chunk(2, 2);

    for (int c = 0; c < C; ++c) {
        const int s = c % NSTG;
        if (c + 3 <= C) cp_wait<2>();
        else if (c + 2 == C) cp_wait<1>();
        else cp_wait<0>();
        __syncthreads();

        const uint32_t st = sb + s * STG_BYTES;
        const uint32_t ahb = st + OFF_AH;
        const uint32_t alb = st + OFF_AL;
        const uint32_t bbb = st;

        #pragma unroll
        for (int ks = 0; ks < 4; ++ks) {
            const int kb = ks * 32;
            uint32_t bf[NAT][2];
            #pragma unroll
            for (int nb = 0; nb < NAT / 2; ++nb) {
                uint32_t addr = bbb + swz((b_row + nb * 16) * 128 + kb + b_kb);
                ldm_x4(bf[nb * 2][0], bf[nb * 2][1],
                       bf[nb * 2 + 1][0], bf[nb * 2 + 1][1], addr);
            }
            // hi plane
            #pragma unroll
            for (int ma = 0; ma < MAT; ++ma) {
                uint32_t a0, a1, a2, a3;
                ldm_x4(a0, a1, a2, a3,
                       ahb + swz((a_row + ma * 16) * 128 + kb + a_kb));
                #pragma unroll
                for (int na = 0; na < NAT; ++na)
                    mma_f16(acc[ma][na][0], acc[ma][na][1],
                            acc[ma][na][2], acc[ma][na][3],
                            a0, a1, a2, a3, bf[na][0], bf[na][1]);
            }
            // lo plane
            if (NA == 2) {
                #pragma unroll
                for (int ma = 0; ma < MAT; ++ma) {
                    uint32_t a0, a1, a2, a3;
                    ldm_x4(a0, a1, a2, a3,
                           alb + swz((a_row + ma * 16) * 128 + kb + a_kb));
                    #pragma unroll
                    for (int na = 0; na < NAT; ++na)
                        mma_f16(acc[ma][na][0], acc[ma][na][1],
                                acc[ma][na][2], acc[ma][na][3],
                                a0, a1, a2, a3, bf[na][0], bf[na][1]);
                }
            }
        }
        __syncthreads();
        if (c + 3 < C) load_chunk(c + 3, s);
    }

    // Epilogue
    const int er = row0 + wr * WM + (lane >> 2);
    const int ec = col0 + wc * WN + (lane & 3) * 2;
    #pragma unroll
    for (int ma = 0; ma < MAT; ++ma) {
        #pragma unroll
        for (int na = 0; na < NAT; ++na) {
            const int r0r = er + ma * 16;
            const int cc = ec + na * 8;
            #pragma unroll
            for (int half_ = 0; half_ < 2; ++half_) {
                const int rr = r0r + half_ * 8;
                float v0 = acc[ma][na][half_ * 2 + 0];
                float v1 = acc[ma][na][half_ * 2 + 1];
                if (EPI == 3) {
                    v0 = lookup_gelu(v0);
                    v1 = lookup_gelu(v1);
                    *reinterpret_cast<__half2*>(outS + (size_t)rr * Ntot + cc) =
                        __floats2half2_rn(v0, v1);
                } else {
                    if (EPI == 1 && cc < phiN) { v0 = phi_fn(v0); v1 = phi_fn(v1); }
                    if (EPI == 2) {
                        const float2 rv = *reinterpret_cast<const float2*>(
                            res + (size_t)rr * Ntot + cc);
                        v0 += rv.x; v1 += rv.y;
                    }
                    float2 o; o.x = v0; o.y = v1;
                    *reinterpret_cast<float2*>(outF + (size_t)rr * Ntot + cc) = o;
                }
            }
        }
    }
}

// ---------------------------------------------------------------------------
// Fused prep: blocks [0,12288) transpose all 6 weights; [12288,20480) LN1
// ---------------------------------------------------------------------------
__global__ __launch_bounds__(256)
void prep_kernel(const float* __restrict__ x,
                 const float* __restrict__ ln1g, const float* __restrict__ ln1b,
                 const float* __restrict__ wq, const float* __restrict__ wk,
                 const float* __restrict__ wv, const float* __restrict__ wo,
                 const float* __restrict__ w1, const float* __restrict__ w2,
                 __half* __restrict__ wqkvt, __half* __restrict__ wot,
                 __half* __restrict__ w1t, __half* __restrict__ w2t,
                 __half* __restrict__ h2)
{
    __shared__ float shm[32 * 33];      // transpose tile OR LN red buffer
    const int b = blockIdx.x;

    if (b >= 12288) {
        // LN1 path
        ln_row_body(x, ln1g, ln1b, h2, b - 12288, threadIdx.x, shm);
        return;
    }

    // transpose path
    const float* src;
    __half* dst;
    int K, N, k0, n0;
    if (b < 4096) {
        const int w = b >> 10, r = b & 1023;
        K = 1024; N = 1024;
        src = (w == 0) ? wq : (w == 1) ? wk : (w == 2) ? wv : wo;
        dst = (w < 3) ? (wqkvt + (size_t)w * D_ * D_) : wot;
        k0 = (r & 31) * 32; n0 = (r >> 5) * 32;
    } else if (b < 8192) {
        const int r = b - 4096;
        K = 1024; N = 4096; src = w1; dst = w1t;
        k0 = (r & 31) * 32; n0 = (r >> 5) * 32;
    } else {
        const int r = b - 8192;
        K = 4096; N = 1024; src = w2; dst = w2t;
        k0 = (r & 127) * 32; n0 = (r >> 7) * 32;
    }

    float (*t)[33] = reinterpret_cast<float (*)[33]>(shm);
    const int tx = threadIdx.x & 31, ty = threadIdx.x >> 5;
    #pragma unroll
    for (int i = 0; i < 4; ++i)
        t[ty + i * 8][tx] = src[(size_t)(k0 + ty + i * 8) * N + n0 + tx];
    __syncthreads();
    #pragma unroll
    for (int i = 0; i < 4; ++i)
        dst[(size_t)(n0 + ty + i * 8) * K + k0 + tx] =
            __float2half_rn(t[tx][ty + i * 8]);
}

// ---------------------------------------------------------------------------
// Standalone LN (for LN2)
// ---------------------------------------------------------------------------
__global__ __launch_bounds__(256)
void ln_split_kernel(const float* __restrict__ x, const float* __restrict__ g,
                     const float* __restrict__ bb, __half* __restrict__ y2)
{
    __shared__ float red[8];
    ln_row_body(x, g, bb, y2, blockIdx.x, threadIdx.x, red);
}

// ---------------------------------------------------------------------------
// kv partials: 128 threads/CTA, 8x4 per-thread tile (R14 config)
// grid (64 bh, KVCH chunks)
// ---------------------------------------------------------------------------
#define QKV_LD (3 * D_)
__global__ __launch_bounds__(128)
void kv_part_kernel(const float* __restrict__ qkv,
                    float* __restrict__ kvpart, float* __restrict__ zpart)
{
    const int bh = blockIdx.x;
    const int ch = blockIdx.y;
    const int b = bh >> 4, h = bh & 15;
    const int schunk = S_ / KVCH;        // 128
    const float* Kp = qkv + (size_t)b * S_ * QKV_LD + D_ + h * DH_
                      + (size_t)ch * schunk * QKV_LD;
    const float* Vp = Kp + D_;

    __shared__ float Ks[32][DH_];
    __shared__ float Vs[32][DH_];

    const int tid = threadIdx.x;         // 0..127
    const int tx = tid & 15, ty = tid >> 4;

    float acc[8][4];
    #pragma unroll
    for (int i = 0; i < 8; i++)
        #pragma unroll
        for (int j = 0; j < 4; j++) acc[i][j] = 0.0f;
    float zacc = 0.0f;

    for (int s0 = 0; s0 < schunk; s0 += 32) {
        #pragma unroll
        for (int i = 0; i < 4; i++) {
            int jj = i * 128 + tid;
            int r = jj >> 4, c4 = jj & 15;
            *reinterpret_cast<float4*>(&Ks[r][c4 * 4]) =
                *reinterpret_cast<const float4*>(&Kp[(size_t)(s0 + r) * QKV_LD + c4 * 4]);
            *reinterpret_cast<float4*>(&Vs[r][c4 * 4]) =
                *reinterpret_cast<const float4*>(&Vp[(size_t)(s0 + r) * QKV_LD + c4 * 4]);
        }
        __syncthreads();
        #pragma unroll 4
        for (int s = 0; s < 32; s++) {
            float a[8], bv[4];
            *reinterpret_cast<float4*>(&a[0]) =
                *reinterpret_cast<const float4*>(&Ks[s][ty * 8]);
            *reinterpret_cast<float4*>(&a[4]) =
                *reinterpret_cast<const float4*>(&Ks[s][ty * 8 + 4]);
            *reinterpret_cast<float4*>(&bv[0]) =
                *reinterpret_cast<const float4*>(&Vs[s][tx * 4]);
            #pragma unroll
            for (int i = 0; i < 8; i++)
                #pragma unroll
                for (int j = 0; j < 4; j++) acc[i][j] += a[i] * bv[j];
        }
        if (tid < DH_) {
            #pragma unroll 4
            for (int s = 0; s < 32; s++) zacc += Ks[s][tid];
        }
        __syncthreads();
    }

    float* kvp = kvpart + ((size_t)ch * 64 + bh) * DH_ * DH_;
    #pragma unroll
    for (int i = 0; i < 8; i++)
        *reinterpret_cast<float4*>(&kvp[(ty * 8 + i) * DH_ + tx * 4]) =
            *reinterpret_cast<const float4*>(&acc[i][0]);
    if (tid < DH_) zpart[((size_t)ch * 64 + bh) * DH_ + tid] = zacc;
}

// Deterministic fixed-order reduce, parallelized: grid (64 bh, 4 slices)
__global__ __launch_bounds__(256)
void kv_reduce_kernel(const float* __restrict__ kvpart, const float* __restrict__ zpart,
                      float* __restrict__ kv, float* __restrict__ z)
{
    const int bh = blockIdx.x;
    const int sl = blockIdx.y;
    const int tid = threadIdx.x;
    const int idx0 = sl * 1024;
    #pragma unroll
    for (int i = 0; i < 4; ++i) {
        int idx = idx0 + i * 256 + tid;
        float s = 0.0f;
        #pragma unroll
        for (int ch = 0; ch < KVCH; ++ch)
            s += kvpart[((size_t)ch * 64 + bh) * DH_ * DH_ + idx];
        kv[(size_t)bh * DH_ * DH_ + idx] = s;
    }
    if (sl == 0 && tid < DH_) {
        float s = 0.0f;
        #pragma unroll
        for (int ch = 0; ch < KVCH; ++ch)
            s += zpart[((size_t)ch * 64 + bh) * DH_ + tid];
        z[bh * DH_ + tid] = s;
    }
}

// ---------------------------------------------------------------------------
// attn out -> split fp16 [M, 2*D]
// ---------------------------------------------------------------------------
__global__ __launch_bounds__(128)
void attn_kernel(const float* __restrict__ qkv, const float* __restrict__ kv,
                 const float* __restrict__ z, __half* __restrict__ out2)
{
    const int bh = blockIdx.x;
    const int b = bh >> 4, h = bh & 15;
    __shared__ float kvs[DH_ * DH_];
    __shared__ float zs[DH_];
    const int tid = threadIdx.x;

    const float4* kvg = reinterpret_cast<const float4*>(kv + (size_t)bh * DH_ * DH_);
    #pragma unroll
    for (int i = 0; i < 8; i++)
        reinterpret_cast<float4*>(kvs)[tid + i * 128] = kvg[tid + i * 128];
    if (tid < 16)
        reinterpret_cast<float4*>(zs)[tid] =
            reinterpret_cast<const float4*>(z + bh * DH_)[tid];
    __syncthreads();

    const int s = blockIdx.y * 128 + tid;
    const float* qr = qkv + (size_t)(b * S_ + s) * QKV_LD + h * DH_;
    float pq[DH_];
    #pragma unroll
    for (int i = 0; i < 16; i++)
        reinterpret_cast<float4*>(pq)[i] = reinterpret_cast<const float4*>(qr)[i];

    float acc[DH_];
    #pragma unroll
    for (int e = 0; e < DH_; e++) acc[e] = 0.0f;
    float den = 1e-6f;

    #pragma unroll 8
    for (int d = 0; d < DH_; d++) {
        float a = pq[d];
        den += a * zs[d];
        const float4* kr = reinterpret_cast<const float4*>(&kvs[d * DH_]);
        #pragma unroll
        for (int e4 = 0; e4 < 16; e4++) {
            float4 kk = kr[e4];
            acc[e4 * 4 + 0] += a * kk.x;
            acc[e4 * 4 + 1] += a * kk.y;
            acc[e4 * 4 + 2] += a * kk.z;
            acc[e4 * 4 + 3] += a * kk.w;
        }
    }

    const float inv = __fdiv_rn(1.0f, den);
    size_t base = (size_t)(b * S_ + s) * (2 * D_) + h * DH_;
    #pragma unroll
    for (int e = 0; e < DH_; e += 2) {
        __half h0, l0, h1, l1;
        split_f16(acc[e] * inv, h0, l0);
        split_f16(acc[e + 1] * inv, h1, l1);
        __half2 hp; hp.x = h0; hp.y = h1;
        __half2 lp; lp.x = l0; lp.y = l1;
        *reinterpret_cast<__half2*>(out2 + base + e) = hp;
        *reinterpret_cast<__half2*>(out2 + base + D_ + e) = lp;
    }
}

// ---------------------------------------------------------------------------
// Launch
// ---------------------------------------------------------------------------
extern "C" void kernel_launch(void* const* d_in, const int* in_sizes, int n_in,
                              void* d_out, int out_size)
{
    const float* x    = (const float*)d_in[0];
    const float* ln1g = (const float*)d_in[1];
    const float* ln1b = (const float*)d_in[2];
    const float* wq   = (const float*)d_in[3];
    const float* wk   = (const float*)d_in[4];
    const float* wv   = (const float*)d_in[5];
    const float* wo   = (const float*)d_in[6];
    const float* ln2g = (const float*)d_in[7];
    const float* ln2b = (const float*)d_in[8];
    const float* w1   = (const float*)d_in[9];
    const float* w2   = (const float*)d_in[10];
    float* out = (float*)d_out;

    __half *h2, *attn2, *a1, *wqkvt, *wot, *w1t, *w2t;
    float *qkv, *x2, *kvp, *zp, *kvpart, *zpart;
    cudaGetSymbolAddress((void**)&h2,     g_h2);
    cudaGetSymbolAddress((void**)&attn2,  g_attn2);
    cudaGetSymbolAddress((void**)&a1,     g_a1);
    cudaGetSymbolAddress((void**)&wqkvt,  g_wqkvt);
    cudaGetSymbolAddress((void**)&wot,    g_wot);
    cudaGetSymbolAddress((void**)&w1t,    g_w1t);
    cudaGetSymbolAddress((void**)&w2t,    g_w2t);
    cudaGetSymbolAddress((void**)&qkv,    g_qkv);
    cudaGetSymbolAddress((void**)&x2,     g_x2);
    cudaGetSymbolAddress((void**)&kvp,    g_kv);
    cudaGetSymbolAddress((void**)&zp,     g_z);
    cudaGetSymbolAddress((void**)&kvpart, g_kvpart);
    cudaGetSymbolAddress((void**)&zpart,  g_zpart);

    cudaFuncSetAttribute(mma_gemm<1, 2, 128, 192>,
                         cudaFuncAttributeMaxDynamicSharedMemorySize,
                         SMEM_TOTAL_(2, 128, 192));
    cudaFuncSetAttribute(mma_gemm<2, 2, 64, 128>,
                         cudaFuncAttributeMaxDynamicSharedMemorySize,
                         SMEM_TOTAL_(2, 64, 128));
    cudaFuncSetAttribute(mma_gemm<3, 2, 128, 256>,
                         cudaFuncAttributeMaxDynamicSharedMemorySize,
                         SMEM_TOTAL_(2, 128, 256));
    cudaFuncSetAttribute(mma_gemm<2, 1, 64, 128>,
                         cudaFuncAttributeMaxDynamicSharedMemorySize,
                         SMEM_TOTAL_(1, 64, 128));

    // 0. fused prep: 6 weight transposes + LN1 in one launch
    prep_kernel<<<20480, 256>>>(x, ln1g, ln1b, wq, wk, wv, wo, w1, w2,
                                wqkvt, wot, w1t, w2t, h2);

    // 1. fused qkv = h2 @ [wq|wk|wv]; phi for cols < 2D (q,k). 1024 CTAs.
    dim3 gQKV(3 * D_ / 192, M_ / 128);
    mma_gemm<1, 2, 128, 192><<<gQKV, 256, SMEM_TOTAL_(2, 128, 192)>>>(
        h2, wqkvt, D_, 3 * D_, 2 * D_, nullptr, qkv, nullptr);

    // 2. kv/z partials (1024 CTAs, 8x4 tiles @128thr) + parallel reduce
    kv_part_kernel<<<dim3(B_ * H_, KVCH), 128>>>(qkv, kvpart, zpart);
    kv_reduce_kernel<<<dim3(B_ * H_, 4), 256>>>(kvpart, zpart, kvp, zp);

    // 3. attn -> split fp16
    attn_kernel<<<dim3(B_ * H_, S_ / 128), 128>>>(qkv, kvp, zp, attn2);

    // 4. x2 = x + attn @ wo   (64x128 tiles -> 1024 CTAs)
    dim3 gWO(D_ / 128, M_ / 64);
    mma_gemm<2, 2, 64, 128><<<gWO, 256, SMEM_TOTAL_(2, 64, 128)>>>(
        attn2, wot, D_, D_, 0, x, x2, nullptr);

    // 5. h2 = split(LN2(x2))
    ln_split_kernel<<<M_, 256>>>(x2, ln2g, ln2b, h2);

    // 6. a1 = fp16(lookup(h2 @ w1))  (128x256 tiles -> 1024 CTAs)
    dim3 gF(FF_ / 256, M_ / 128);
    mma_gemm<3, 2, 128, 256><<<gF, 256, SMEM_TOTAL_(2, 128, 256)>>>(
        h2, w1t, D_, FF_, 0, nullptr, nullptr, a1);

    // 7. out = x2 + a1 @ w2  (single fp16 A, 64x128 tiles -> 1024 CTAs)
    mma_gemm<2, 1, 64, 128><<<gWO, 256, SMEM_TOTAL_(1, 64, 128)>>>(
        a1, w2t, FF_, D_, 0, x2, out, nullptr);
}

// round 17
// speedup vs baseline: 1.0073x; 1.0012x over previous
#include <cuda_runtime.h>
#include <cuda_fp16.h>
#include <math.h>
#include <stdint.h>

// ---------------------------------------------------------------------------
// Problem constants
// ---------------------------------------------------------------------------
#define B_  4
#define S_  2048
#define D_  1024
#define H_  16
#define DH_ 64
#define FF_ 4096
#define M_  (B_ * S_)          // 8192 rows
#define KVCH 16

// ---------------------------------------------------------------------------
// Scratch (device globals)
// ---------------------------------------------------------------------------
__device__ __half g_h2[M_ * 2 * D_];            // LN output, split (hi | lo)
__device__ __half g_attn2[M_ * 2 * D_];         // attention output, split
__device__ __half g_a1[(size_t)M_ * FF_];       // lookup out, fp16 single
__device__ float g_qkv[(size_t)M_ * 3 * D_];    // fused q|k|v (phi on q,k)
__device__ float g_x2[M_ * D_];
__device__ float g_kv[B_ * H_ * DH_ * DH_];
__device__ float g_z[B_ * H_ * DH_];
__device__ float g_kvpart[KVCH * B_ * H_ * DH_ * DH_];
__device__ float g_zpart[KVCH * B_ * H_ * DH_];
// transposed fp16 weights (K-major rows: wt[n,k] = w[k,n])
__device__ __half g_wqkvt[3 * D_ * D_];
__device__ __half g_wot[D_ * D_];
__device__ __half g_w1t[FF_ * D_];
__device__ __half g_w2t[D_ * FF_];

// ---------------------------------------------------------------------------
// PTX helpers (portable ISA: cp.async, ldmatrix, mma.sync)
// ---------------------------------------------------------------------------
__device__ __forceinline__ uint32_t smem_u32(const void* p) {
    uint32_t a;
    asm("{ .reg .u64 t; cvta.to.shared.u64 t, %1; cvt.u32.u64 %0, t; }"
        : "=r"(a) : "l"(p));
    return a;
}
__device__ __forceinline__ void cp_async16(uint32_t dst, const void* src) {
    asm volatile("cp.async.cg.shared.global [%0], [%1], 16;" :: "r"(dst), "l"(src));
}
#define CP_COMMIT() asm volatile("cp.async.commit_group;" ::: "memory")
template <int N>
__device__ __forceinline__ void cp_wait() {
    asm volatile("cp.async.wait_group %0;" :: "n"(N) : "memory");
}
__device__ __forceinline__ void ldm_x4(uint32_t& r0, uint32_t& r1, uint32_t& r2,
                                       uint32_t& r3, uint32_t addr) {
    asm volatile("ldmatrix.sync.aligned.m8n8.x4.shared.b16 {%0,%1,%2,%3}, [%4];"
                 : "=r"(r0), "=r"(r1), "=r"(r2), "=r"(r3) : "r"(addr));
}
__device__ __forceinline__ void mma_f16(float& c0, float& c1, float& c2, float& c3,
                                        uint32_t a0, uint32_t a1, uint32_t a2,
                                        uint32_t a3, uint32_t b0, uint32_t b1) {
    asm volatile(
        "mma.sync.aligned.m16n8k16.row.col.f32.f16.f16.f32 "
        "{%0,%1,%2,%3}, {%4,%5,%6,%7}, {%8,%9}, {%0,%1,%2,%3};"
        : "+f"(c0), "+f"(c1), "+f"(c2), "+f"(c3)
        : "r"(a0), "r"(a1), "r"(a2), "r"(a3), "r"(b0), "r"(b1));
}
__device__ __forceinline__ uint32_t swz(uint32_t o) { return o ^ ((o >> 3) & 0x70u); }

// ---------------------------------------------------------------------------
// Math helpers
// ---------------------------------------------------------------------------
__device__ __forceinline__ float phi_fn(float v) {
    return v > 0.0f ? v + 1.0f : expf(v);
}
__device__ __forceinline__ float lookup_gelu(float v) {
    float r = rintf(__fdiv_rn(v, 0.1f));
    r = fminf(fmaxf(r, -128.0f), 127.0f);
    float xq = r * 0.1f;
    float inner = 0.7978845608028654f * (xq + 0.044715f * xq * xq * xq);
    return 0.5f * xq * (1.0f + tanhf(inner));
}
__device__ __forceinline__ void split_f16(float v, __half& hi, __half& lo) {
    hi = __float2half_rn(v);
    lo = __float2half_rn(v - __half2float(hi));
}

// ---------------------------------------------------------------------------
// LN body (shared by fused prep kernel and standalone LN kernel)
// ---------------------------------------------------------------------------
__device__ __forceinline__ void ln_row_body(const float* __restrict__ x,
                                            const float* __restrict__ g,
                                            const float* __restrict__ bb,
                                            __half* __restrict__ y2,
                                            int row, int tid, float* red)
{
    float4 v = reinterpret_cast<const float4*>(x + (size_t)row * D_)[tid];

    float s = v.x + v.y + v.z + v.w;
    #pragma unroll
    for (int o = 16; o > 0; o >>= 1) s += __shfl_xor_sync(0xffffffffu, s, o);
    if ((tid & 31) == 0) red[tid >> 5] = s;
    __syncthreads();
    s = 0.0f;
    #pragma unroll
    for (int i = 0; i < 8; i++) s += red[i];
    const float mean = s * (1.0f / D_);
    __syncthreads();

    float d0 = v.x - mean, d1 = v.y - mean, d2 = v.z - mean, d3 = v.w - mean;
    float s2 = d0 * d0 + d1 * d1 + d2 * d2 + d3 * d3;
    #pragma unroll
    for (int o = 16; o > 0; o >>= 1) s2 += __shfl_xor_sync(0xffffffffu, s2, o);
    if ((tid & 31) == 0) red[tid >> 5] = s2;
    __syncthreads();
    s2 = 0.0f;
    #pragma unroll
    for (int i = 0; i < 8; i++) s2 += red[i];
    const float rs = rsqrtf(s2 * (1.0f / D_) + 1e-5f);

    float4 gg = reinterpret_cast<const float4*>(g)[tid];
    float4 bv = reinterpret_cast<const float4*>(bb)[tid];
    float o0 = d0 * rs * gg.x + bv.x;
    float o1 = d1 * rs * gg.y + bv.y;
    float o2 = d2 * rs * gg.z + bv.z;
    float o3 = d3 * rs * gg.w + bv.w;

    size_t base = (size_t)row * (2 * D_) + tid * 4;
    __half h0, l0, h1, l1, h2, l2, h3, l3;
    split_f16(o0, h0, l0); split_f16(o1, h1, l1);
    split_f16(o2, h2, l2); split_f16(o3, h3, l3);
    __half2 hp0; hp0.x = h0; hp0.y = h1;
    __half2 hp1; hp1.x = h2; hp1.y = h3;
    __half2 lp0; lp0.x = l0; lp0.y = l1;
    __half2 lp1; lp1.x = l2; lp1.y = l3;
    *reinterpret_cast<__half2*>(y2 + base) = hp0;
    *reinterpret_cast<__half2*>(y2 + base + 2) = hp1;
    *reinterpret_cast<__half2*>(y2 + base + D_) = lp0;
    *reinterpret_cast<__half2*>(y2 + base + D_ + 2) = lp1;
}

// ---------------------------------------------------------------------------
// fp16 split GEMM via mma.sync (tile GBMT x GBNT, both templated)
// ---------------------------------------------------------------------------
#define KC  64
#define NSTG 3
#define TILE_A_(GBMT)   ((GBMT) * 128)
#define TILE_B_(GBNT)   ((GBNT) * 128)
#define STG_BYTES_(NA, GBMT, GBNT)  (TILE_B_(GBNT) + (NA) * TILE_A_(GBMT))
#define SMEM_TOTAL_(NA, GBMT, GBNT) (NSTG * STG_BYTES_(NA, GBMT, GBNT))

template <int EPI, int NA, int GBMT, int GBNT>
__global__ __launch_bounds__(256, 1)
void mma_gemm(const __half* __restrict__ A2, const __half* __restrict__ Bt,
              int K, int Ntot, int phiN, const float* __restrict__ res,
              float* __restrict__ outF, __half* __restrict__ outS)
{
    constexpr int STG_BYTES = STG_BYTES_(NA, GBMT, GBNT);
    constexpr int WM  = GBMT / 2;
    constexpr int WN  = GBNT / 4;
    constexpr int MAT = GBMT / 32;
    constexpr int NAT = GBNT / 32;
    constexpr int OFF_AH = TILE_B_(GBNT);
    constexpr int OFF_AL = TILE_B_(GBNT) + TILE_A_(GBMT);
    extern __shared__ char smem[];
    const uint32_t sb = smem_u32(smem);
    const int tid = threadIdx.x;
    const int wid = tid >> 5;
    const int lane = tid & 31;
    const int wr = wid >> 2;
    const int wc = wid & 3;
    const int row0 = blockIdx.y * GBMT;
    const int col0 = blockIdx.x * GBNT;
    const int lda = NA * K;
    const int C = K / KC;

    const int g = lane >> 3;
    const int l8 = lane & 7;
    const int a_row = wr * WM + (g & 1) * 8 + l8;
    const int a_kb  = (g >> 1) * 16;
    const int b_row = wc * WN + (g >> 1) * 8 + l8;
    const int b_kb  = (g & 1) * 16;

    float acc[MAT][NAT][4];
    #pragma unroll
    for (int i = 0; i < MAT; i++)
        #pragma unroll
        for (int j = 0; j < NAT; j++)
            #pragma unroll
            for (int t = 0; t < 4; t++) acc[i][j][t] = 0.0f;

    auto load_chunk = [&](int c, int s) {
        const uint32_t st = sb + s * STG_BYTES;
        const int k0 = c * KC;
        #pragma unroll
        for (int i = 0; i < NAT; ++i) {
            int seg = i * 256 + tid;
            int r = seg >> 3, c8 = seg & 7;
            cp_async16(st + swz(r * 128 + c8 * 16),
                       Bt + (size_t)(col0 + r) * K + k0 + c8 * 8);
        }
        #pragma unroll
        for (int i = 0; i < MAT; ++i) {
            int seg = i * 256 + tid;
            int r = seg >> 3, c8 = seg & 7;
            uint32_t doff = swz(r * 128 + c8 * 16);
            const __half* ah = A2 + (size_t)(row0 + r) * lda + k0 + c8 * 8;
            cp_async16(st + OFF_AH + doff, ah);
            if (NA == 2) cp_async16(st + OFF_AL + doff, ah + K);
        }
        CP_COMMIT();
    };

    load_chunk(0, 0);
    if (C > 1) load_chunk(1, 1);
    if (C > 2) load_chunk(2, 2);

    for (int c = 0; c < C; ++c) {
        const int s = c % NSTG;
        if (c + 3 <= C) cp_wait<2>();
        else if (c + 2 == C) cp_wait<1>();
        else cp_wait<0>();
        __syncthreads();

        const uint32_t st = sb + s * STG_BYTES;
        const uint32_t ahb = st + OFF_AH;
        const uint32_t alb = st + OFF_AL;
        const uint32_t bbb = st;

        #pragma unroll
        for (int ks = 0; ks < 4; ++ks) {
            const int kb = ks * 32;
            uint32_t bf[NAT][2];
            #pragma unroll
            for (int nb = 0; nb < NAT / 2; ++nb) {
                uint32_t addr = bbb + swz((b_row + nb * 16) * 128 + kb + b_kb);
                ldm_x4(bf[nb * 2][0], bf[nb * 2][1],
                       bf[nb * 2 + 1][0], bf[nb * 2 + 1][1], addr);
            }
            // hi plane
            #pragma unroll
            for (int ma = 0; ma < MAT; ++ma) {
                uint32_t a0, a1, a2, a3;
                ldm_x4(a0, a1, a2, a3,
                       ahb + swz((a_row + ma * 16) * 128 + kb + a_kb));
                #pragma unroll
                for (int na = 0; na < NAT; ++na)
                    mma_f16(acc[ma][na][0], acc[ma][na][1],
                            acc[ma][na][2], acc[ma][na][3],
                            a0, a1, a2, a3, bf[na][0], bf[na][1]);
            }
            // lo plane
            if (NA == 2) {
                #pragma unroll
                for (int ma = 0; ma < MAT; ++ma) {
                    uint32_t a0, a1, a2, a3;
                    ldm_x4(a0, a1, a2, a3,
                           alb + swz((a_row + ma * 16) * 128 + kb + a_kb));
                    #pragma unroll
                    for (int na = 0; na < NAT; ++na)
                        mma_f16(acc[ma][na][0], acc[ma][na][1],
                                acc[ma][na][2], acc[ma][na][3],
                                a0, a1, a2, a3, bf[na][0], bf[na][1]);
                }
            }
        }
        __syncthreads();
        if (c + 3 < C) load_chunk(c + 3, s);
    }

    // Epilogue
    const int er = row0 + wr * WM + (lane >> 2);
    const int ec = col0 + wc * WN + (lane & 3) * 2;
    #pragma unroll
    for (int ma = 0; ma < MAT; ++ma) {
        #pragma unroll
        for (int na = 0; na < NAT; ++na) {
            const int r0r = er + ma * 16;
            const int cc = ec + na * 8;
            #pragma unroll
            for (int half_ = 0; half_ < 2; ++half_) {
                const int rr = r0r + half_ * 8;
                float v0 = acc[ma][na][half_ * 2 + 0];
                float v1 = acc[ma][na][half_ * 2 + 1];
                if (EPI == 3) {
                    v0 = lookup_gelu(v0);
                    v1 = lookup_gelu(v1);
                    *reinterpret_cast<__half2*>(outS + (size_t)rr * Ntot + cc) =
                        __floats2half2_rn(v0, v1);
                } else {
                    if (EPI == 1 && cc < phiN) { v0 = phi_fn(v0); v1 = phi_fn(v1); }
                    if (EPI == 2) {
                        const float2 rv = *reinterpret_cast<const float2*>(
                            res + (size_t)rr * Ntot + cc);
                        v0 += rv.x; v1 += rv.y;
                    }
                    float2 o; o.x = v0; o.y = v1;
                    *reinterpret_cast<float2*>(outF + (size_t)rr * Ntot + cc) = o;
                }
            }
        }
    }
}

// ---------------------------------------------------------------------------
// Fused prep: blocks [0,12288) transpose all 6 weights; [12288,20480) LN1
// ---------------------------------------------------------------------------
__global__ __launch_bounds__(256)
void prep_kernel(const float* __restrict__ x,
                 const float* __restrict__ ln1g, const float* __restrict__ ln1b,
                 const float* __restrict__ wq, const float* __restrict__ wk,
                 const float* __restrict__ wv, const float* __restrict__ wo,
                 const float* __restrict__ w1, const float* __restrict__ w2,
                 __half* __restrict__ wqkvt, __half* __restrict__ wot,
                 __half* __restrict__ w1t, __half* __restrict__ w2t,
                 __half* __restrict__ h2)
{
    __shared__ float shm[32 * 33];
    const int b = blockIdx.x;

    if (b >= 12288) {
        ln_row_body(x, ln1g, ln1b, h2, b - 12288, threadIdx.x, shm);
        return;
    }

    const float* src;
    __half* dst;
    int K, N, k0, n0;
    if (b < 4096) {
        const int w = b >> 10, r = b & 1023;
        K = 1024; N = 1024;
        src = (w == 0) ? wq : (w == 1) ? wk : (w == 2) ? wv : wo;
        dst = (w < 3) ? (wqkvt + (size_t)w * D_ * D_) : wot;
        k0 = (r & 31) * 32; n0 = (r >> 5) * 32;
    } else if (b < 8192) {
        const int r = b - 4096;
        K = 1024; N = 4096; src = w1; dst = w1t;
        k0 = (r & 31) * 32; n0 = (r >> 5) * 32;
    } else {
        const int r = b - 8192;
        K = 4096; N = 1024; src = w2; dst = w2t;
        k0 = (r & 127) * 32; n0 = (r >> 7) * 32;
    }

    float (*t)[33] = reinterpret_cast<float (*)[33]>(shm);
    const int tx = threadIdx.x & 31, ty = threadIdx.x >> 5;
    #pragma unroll
    for (int i = 0; i < 4; ++i)
        t[ty + i * 8][tx] = src[(size_t)(k0 + ty + i * 8) * N + n0 + tx];
    __syncthreads();
    #pragma unroll
    for (int i = 0; i < 4; ++i)
        dst[(size_t)(n0 + ty + i * 8) * K + k0 + tx] =
            __float2half_rn(t[tx][ty + i * 8]);
}

// ---------------------------------------------------------------------------
// Standalone LN (for LN2)
// ---------------------------------------------------------------------------
__global__ __launch_bounds__(256)
void ln_split_kernel(const float* __restrict__ x, const float* __restrict__ g,
                     const float* __restrict__ bb, __half* __restrict__ y2)
{
    __shared__ float red[8];
    ln_row_body(x, g, bb, y2, blockIdx.x, threadIdx.x, red);
}

// ---------------------------------------------------------------------------
// kv partials: 128 threads/CTA, 8x4 per-thread tile
// grid (64 bh, KVCH chunks)
// ---------------------------------------------------------------------------
#define QKV_LD (3 * D_)
__global__ __launch_bounds__(128)
void kv_part_kernel(const float* __restrict__ qkv,
                    float* __restrict__ kvpart, float* __restrict__ zpart)
{
    const int bh = blockIdx.x;
    const int ch = blockIdx.y;
    const int b = bh >> 4, h = bh & 15;
    const int schunk = S_ / KVCH;        // 128
    const float* Kp = qkv + (size_t)b * S_ * QKV_LD + D_ + h * DH_
                      + (size_t)ch * schunk * QKV_LD;
    const float* Vp = Kp + D_;

    __shared__ float Ks[32][DH_];
    __shared__ float Vs[32][DH_];

    const int tid = threadIdx.x;         // 0..127
    const int tx = tid & 15, ty = tid >> 4;

    float acc[8][4];
    #pragma unroll
    for (int i = 0; i < 8; i++)
        #pragma unroll
        for (int j = 0; j < 4; j++) acc[i][j] = 0.0f;
    float zacc = 0.0f;

    for (int s0 = 0; s0 < schunk; s0 += 32) {
        #pragma unroll
        for (int i = 0; i < 4; i++) {
            int jj = i * 128 + tid;
            int r = jj >> 4, c4 = jj & 15;
            *reinterpret_cast<float4*>(&Ks[r][c4 * 4]) =
                *reinterpret_cast<const float4*>(&Kp[(size_t)(s0 + r) * QKV_LD + c4 * 4]);
            *reinterpret_cast<float4*>(&Vs[r][c4 * 4]) =
                *reinterpret_cast<const float4*>(&Vp[(size_t)(s0 + r) * QKV_LD + c4 * 4]);
        }
        __syncthreads();
        #pragma unroll 4
        for (int s = 0; s < 32; s++) {
            float a[8], bv[4];
            *reinterpret_cast<float4*>(&a[0]) =
                *reinterpret_cast<const float4*>(&Ks[s][ty * 8]);
            *reinterpret_cast<float4*>(&a[4]) =
                *reinterpret_cast<const float4*>(&Ks[s][ty * 8 + 4]);
            *reinterpret_cast<float4*>(&bv[0]) =
                *reinterpret_cast<const float4*>(&Vs[s][tx * 4]);
            #pragma unroll
            for (int i = 0; i < 8; i++)
                #pragma unroll
                for (int j = 0; j < 4; j++) acc[i][j] += a[i] * bv[j];
        }
        if (tid < DH_) {
            #pragma unroll 4
            for (int s = 0; s < 32; s++) zacc += Ks[s][tid];
        }
        __syncthreads();
    }

    float* kvp = kvpart + ((size_t)ch * 64 + bh) * DH_ * DH_;
    #pragma unroll
    for (int i = 0; i < 8; i++)
        *reinterpret_cast<float4*>(&kvp[(ty * 8 + i) * DH_ + tx * 4]) =
            *reinterpret_cast<const float4*>(&acc[i][0]);
    if (tid < DH_) zpart[((size_t)ch * 64 + bh) * DH_ + tid] = zacc;
}

// Deterministic fixed-order reduce; grid (64 bh, 16 slices), 1 elem/thread
__global__ __launch_bounds__(256)
void kv_reduce_kernel(const float* __restrict__ kvpart, const float* __restrict__ zpart,
                      float* __restrict__ kv, float* __restrict__ z)
{
    const int bh = blockIdx.x;
    const int sl = blockIdx.y;           // 0..15, each 256 kv elements
    const int tid = threadIdx.x;
    const int idx = sl * 256 + tid;
    float s = 0.0f;
    #pragma unroll
    for (int ch = 0; ch < KVCH; ++ch)
        s += kvpart[((size_t)ch * 64 + bh) * DH_ * DH_ + idx];
    kv[(size_t)bh * DH_ * DH_ + idx] = s;
    if (sl == 0 && tid < DH_) {
        float zs = 0.0f;
        #pragma unroll
        for (int ch = 0; ch < KVCH; ++ch)
            zs += zpart[((size_t)ch * 64 + bh) * DH_ + tid];
        z[bh * DH_ + tid] = zs;
    }
}

// ---------------------------------------------------------------------------
// attn out -> split fp16 [M, 2*D]
// ---------------------------------------------------------------------------
__global__ __launch_bounds__(128)
void attn_kernel(const float* __restrict__ qkv, const float* __restrict__ kv,
                 const float* __restrict__ z, __half* __restrict__ out2)
{
    const int bh = blockIdx.x;
    const int b = bh >> 4, h = bh & 15;
    __shared__ float kvs[DH_ * DH_];
    __shared__ float zs[DH_];
    const int tid = threadIdx.x;

    const float4* kvg = reinterpret_cast<const float4*>(kv + (size_t)bh * DH_ * DH_);
    #pragma unroll
    for (int i = 0; i < 8; i++)
        reinterpret_cast<float4*>(kvs)[tid + i * 128] = kvg[tid + i * 128];
    if (tid < 16)
        reinterpret_cast<float4*>(zs)[tid] =
            reinterpret_cast<const float4*>(z + bh * DH_)[tid];
    __syncthreads();

    const int s = blockIdx.y * 128 + tid;
    const float* qr = qkv + (size_t)(b * S_ + s) * QKV_LD + h * DH_;
    float pq[DH_];
    #pragma unroll
    for (int i = 0; i < 16; i++)
        reinterpret_cast<float4*>(pq)[i] = reinterpret_cast<const float4*>(qr)[i];

    float acc[DH_];
    #pragma unroll
    for (int e = 0; e < DH_; e++) acc[e] = 0.0f;
    float den = 1e-6f;

    #pragma unroll 8
    for (int d = 0; d < DH_; d++) {
        float a = pq[d];
        den += a * zs[d];
        const float4* kr = reinterpret_cast<const float4*>(&kvs[d * DH_]);
        #pragma unroll
        for (int e4 = 0; e4 < 16; e4++) {
            float4 kk = kr[e4];
            acc[e4 * 4 + 0] += a * kk.x;
            acc[e4 * 4 + 1] += a * kk.y;
            acc[e4 * 4 + 2] += a * kk.z;
            acc[e4 * 4 + 3] += a * kk.w;
        }
    }

    const float inv = __fdiv_rn(1.0f, den);
    size_t base = (size_t)(b * S_ + s) * (2 * D_) + h * DH_;
    #pragma unroll
    for (int e = 0; e < DH_; e += 2) {
        __half h0, l0, h1, l1;
        split_f16(acc[e] * inv, h0, l0);
        split_f16(acc[e + 1] * inv, h1, l1);
        __half2 hp; hp.x = h0; hp.y = h1;
        __half2 lp; lp.x = l0; lp.y = l1;
        *reinterpret_cast<__half2*>(out2 + base + e) = hp;
        *reinterpret_cast<__half2*>(out2 + base + D_ + e) = lp;
    }
}

// ---------------------------------------------------------------------------
// Launch
// ---------------------------------------------------------------------------
extern "C" void kernel_launch(void* const* d_in, const int* in_sizes, int n_in,
                              void* d_out, int out_size)
{
    const float* x    = (const float*)d_in[0];
    const float* ln1g = (const float*)d_in[1];
    const float* ln1b = (const float*)d_in[2];
    const float* wq   = (const float*)d_in[3];
    const float* wk   = (const float*)d_in[4];
    const float* wv   = (const float*)d_in[5];
    const float* wo   = (const float*)d_in[6];
    const float* ln2g = (const float*)d_in[7];
    const float* ln2b = (const float*)d_in[8];
    const float* w1   = (const float*)d_in[9];
    const float* w2   = (const float*)d_in[10];
    float* out = (float*)d_out;

    __half *h2, *attn2, *a1, *wqkvt, *wot, *w1t, *w2t;
    float *qkv, *x2, *kvp, *zp, *kvpart, *zpart;
    cudaGetSymbolAddress((void**)&h2,     g_h2);
    cudaGetSymbolAddress((void**)&attn2,  g_attn2);
    cudaGetSymbolAddress((void**)&a1,     g_a1);
    cudaGetSymbolAddress((void**)&wqkvt,  g_wqkvt);
    cudaGetSymbolAddress((void**)&wot,    g_wot);
    cudaGetSymbolAddress((void**)&w1t,    g_w1t);
    cudaGetSymbolAddress((void**)&w2t,    g_w2t);
    cudaGetSymbolAddress((void**)&qkv,    g_qkv);
    cudaGetSymbolAddress((void**)&x2,     g_x2);
    cudaGetSymbolAddress((void**)&kvp,    g_kv);
    cudaGetSymbolAddress((void**)&zp,     g_z);
    cudaGetSymbolAddress((void**)&kvpart, g_kvpart);
    cudaGetSymbolAddress((void**)&zpart,  g_zpart);

    cudaFuncSetAttribute(mma_gemm<1, 2, 128, 192>,
                         cudaFuncAttributeMaxDynamicSharedMemorySize,
                         SMEM_TOTAL_(2, 128, 192));
    cudaFuncSetAttribute(mma_gemm<2, 2, 64, 128>,
                         cudaFuncAttributeMaxDynamicSharedMemorySize,
                         SMEM_TOTAL_(2, 64, 128));
    cudaFuncSetAttribute(mma_gemm<3, 2, 128, 256>,
                         cudaFuncAttributeMaxDynamicSharedMemorySize,
                         SMEM_TOTAL_(2, 128, 256));
    cudaFuncSetAttribute(mma_gemm<2, 1, 64, 128>,
                         cudaFuncAttributeMaxDynamicSharedMemorySize,
                         SMEM_TOTAL_(1, 64, 128));

    // 0. fused prep: 6 weight transposes + LN1 in one launch
    prep_kernel<<<20480, 256>>>(x, ln1g, ln1b, wq, wk, wv, wo, w1, w2,
                                wqkvt, wot, w1t, w2t, h2);

    // 1. fused qkv = h2 @ [wq|wk|wv]; phi for cols < 2D (q,k). 1024 CTAs.
    dim3 gQKV(3 * D_ / 192, M_ / 128);
    mma_gemm<1, 2, 128, 192><<<gQKV, 256, SMEM_TOTAL_(2, 128, 192)>>>(
        h2, wqkvt, D_, 3 * D_, 2 * D_, nullptr, qkv, nullptr);

    // 2. kv/z partials + parallel deterministic reduce (1024 CTAs each)
    kv_part_kernel<<<dim3(B_ * H_, KVCH), 128>>>(qkv, kvpart, zpart);
    kv_reduce_kernel<<<dim3(B_ * H_, 16), 256>>>(kvpart, zpart, kvp, zp);

    // 3. attn -> split fp16
    attn_kernel<<<dim3(B_ * H_, S_ / 128), 128>>>(qkv, kvp, zp, attn2);

    // 4. x2 = x + attn @ wo   (64x128 tiles -> 1024 CTAs)
    dim3 gWO(D_ / 128, M_ / 64);
    mma_gemm<2, 2, 64, 128><<<gWO, 256, SMEM_TOTAL_(2, 64, 128)>>>(
        attn2, wot, D_, D_, 0, x, x2, nullptr);

    // 5. h2 = split(LN2(x2))
    ln_split_kernel<<<M_, 256>>>(x2, ln2g, ln2b, h2);

    // 6. a1 = fp16(lookup(h2 @ w1))  (128x256 tiles -> 1024 CTAs)
    dim3 gF(FF_ / 256, M_ / 128);
    mma_gemm<3, 2, 128, 256><<<gF, 256, SMEM_TOTAL_(2, 128, 256)>>>(
        h2, w1t, D_, FF_, 0, nullptr, nullptr, a1);

    // 7. out = x2 + a1 @ w2  (single fp16 A, 64x128 tiles -> 1024 CTAs)
    mma_gemm<2, 1, 64, 128><<<gWO, 256, SMEM_TOTAL_(1, 64, 128)>>>(
        a1, w2t, FF_, D_, 0, x2, out, nullptr);
}